// round 15
// baseline (speedup 1.0000x reference)
#include <cuda_runtime.h>
#include <cuda_fp16.h>
#include <cstdint>

#define B_    32
#define N_    577
#define H_    12
#define DH_   64
#define DIM_  768
#define INNER 768
#define M_TOT (B_ * N_)   // 18464
#define NEG_MASK (-987654321.0f)
#define LOG2E 1.4426950408889634f

// ---------------- scratch (device globals: no runtime allocation) -------------
__device__ __align__(128) __half g_qh[(size_t)B_ * H_ * N_ * DH_];   // pre-scaled by scale[h]*log2e
__device__ __align__(128) __half g_kh[(size_t)B_ * H_ * N_ * DH_];
__device__ __align__(128) __half g_vh[(size_t)B_ * H_ * N_ * DH_];
__device__ __align__(128) __half g_xh[(size_t)M_TOT * DIM_];
__device__ __align__(128) __half g_atth[(size_t)M_TOT * INNER];
__device__ __align__(128) __half g_wqkvt[(size_t)2304 * DIM_];
__device__ __align__(128) __half g_woutt[(size_t)DIM_ * INNER];

__device__ __forceinline__ uint32_t smem_to_u32(const void* p) {
    uint32_t a;
    asm("{ .reg .u64 t; cvta.to.shared.u64 t, %1; cvt.u32.u64 %0, t; }" : "=r"(a) : "l"(p));
    return a;
}
__device__ __forceinline__ float ex2f(float x) {
    float r;
    asm("ex2.approx.ftz.f32 %0, %1;" : "=f"(r) : "f"(x));
    return r;
}

#define MMA_F16(acc, a0, a1, a2, a3, b0, b1) \
    asm volatile("mma.sync.aligned.m16n8k16.row.col.f32.f16.f16.f32 " \
        "{%0,%1,%2,%3}, {%4,%5,%6,%7}, {%8,%9}, {%0,%1,%2,%3};" \
        : "+f"((acc)[0]), "+f"((acc)[1]), "+f"((acc)[2]), "+f"((acc)[3]) \
        : "r"(a0), "r"(a1), "r"(a2), "r"(a3), "r"(b0), "r"(b1))

#define LDSM_X4(r0, r1, r2, r3, addr) \
    asm volatile("ldmatrix.sync.aligned.m8n8.x4.shared.b16 {%0,%1,%2,%3}, [%4];" \
        : "=r"(r0), "=r"(r1), "=r"(r2), "=r"(r3) : "r"(addr))

#define LDSM_X4_T(r0, r1, r2, r3, addr) \
    asm volatile("ldmatrix.sync.aligned.m8n8.x4.trans.shared.b16 {%0,%1,%2,%3}, [%4];" \
        : "=r"(r0), "=r"(r1), "=r"(r2), "=r"(r3) : "r"(addr))

__device__ __forceinline__ uint32_t pack_h2(float lo, float hi) {
    __half2 h = __floats2half2_rn(lo, hi);
    return *(uint32_t*)&h;
}

// ---------------- HMMA GEMM (proven R10 best) -----------------------------------
__global__ __launch_bounds__(128, 2) void hgemm_mma(
    const __half* __restrict__ A, const __half* __restrict__ Bt,
    int Mrows, int mode, const float* __restrict__ bias,
    const float* __restrict__ qscale, float* __restrict__ Cout)
{
    extern __shared__ char smem[];
    const uint32_t sbase = smem_to_u32(smem);   // 2 bufs x (A 16K + B 16K)

    const int tid = threadIdx.x;
    const int wid = tid >> 5, lid = tid & 31;
    const int n0 = blockIdx.x * 128, m0 = blockIdx.y * 128;
    const int wm = wid >> 1, wn = wid & 1;

    float acc[4][8][4];
#pragma unroll
    for (int mi = 0; mi < 4; mi++)
#pragma unroll
        for (int ni = 0; ni < 8; ni++)
#pragma unroll
            for (int e = 0; e < 4; e++) acc[mi][ni][e] = 0.f;

    auto prefetch = [&](int c, int buf) {
        uint32_t sA = sbase + buf * 32768;
        uint32_t sB = sA + 16384;
#pragma unroll
        for (int i = 0; i < 8; i++) {
            int idx = tid + i * 128;
            int row = idx >> 3, cc = idx & 7;
            uint32_t off = row * 128 + cc * 16;
            uint32_t sw = off ^ ((off >> 3) & 0x70);
            const void* gA = A + (size_t)(m0 + row) * 768 + c * 64 + cc * 8;
            int szA = (m0 + row < Mrows) ? 16 : 0;
            asm volatile("cp.async.cg.shared.global [%0], [%1], 16, %2;"
                         :: "r"(sA + sw), "l"(gA), "r"(szA));
            const void* gB = Bt + (size_t)(n0 + row) * 768 + c * 64 + cc * 8;
            asm volatile("cp.async.cg.shared.global [%0], [%1], 16;"
                         :: "r"(sB + sw), "l"(gB));
        }
        asm volatile("cp.async.commit_group;");
    };

    uint32_t aOff[4], aXor[4], bOff[4], bXor[4];
#pragma unroll
    for (int mi = 0; mi < 4; mi++) {
        int row = wm * 64 + mi * 16 + (lid & 15);
        aOff[mi] = row * 128 + (lid >> 4) * 16;
        aXor[mi] = (aOff[mi] >> 3) & 0x70;
    }
#pragma unroll
    for (int nj = 0; nj < 4; nj++) {
        int row = wn * 64 + nj * 16 + ((lid >> 4) & 1) * 8 + (lid & 7);
        bOff[nj] = row * 128 + ((lid >> 3) & 1) * 16;
        bXor[nj] = (bOff[nj] >> 3) & 0x70;
    }
#define A_ADDR(mi, k) (sA + ((aOff[mi] + (k) * 32) ^ aXor[mi]))
#define B_ADDR(nj, k) (sB + ((bOff[nj] + (k) * 32) ^ bXor[nj]))

    prefetch(0, 0);

    for (int c = 0; c < 12; c++) {
        asm volatile("cp.async.wait_group 0;");
        __syncthreads();
        if (c < 11) prefetch(c + 1, (c + 1) & 1);

        const uint32_t sA = sbase + (c & 1) * 32768;
        const uint32_t sB = sA + 16384;

        uint32_t a[2][4][4], b[2][4];
#pragma unroll
        for (int mi = 0; mi < 4; mi++)
            LDSM_X4(a[0][mi][0], a[0][mi][1], a[0][mi][2], a[0][mi][3],
                    A_ADDR(mi, 0));
        LDSM_X4(b[0][0], b[0][1], b[0][2], b[0][3], B_ADDR(0, 0));

#pragma unroll
        for (int k16 = 0; k16 < 4; k16++) {
#pragma unroll
            for (int nj = 0; nj < 4; nj++) {
                const int cur = (k16 * 4 + nj) & 1, nxt = cur ^ 1;
                const int ka = k16 & 1;
                if (nj < 3) {
                    LDSM_X4(b[nxt][0], b[nxt][1], b[nxt][2], b[nxt][3],
                            B_ADDR(nj + 1, k16));
                } else if (k16 < 3) {
#pragma unroll
                    for (int mi = 0; mi < 4; mi++)
                        LDSM_X4(a[ka ^ 1][mi][0], a[ka ^ 1][mi][1],
                                a[ka ^ 1][mi][2], a[ka ^ 1][mi][3],
                                A_ADDR(mi, k16 + 1));
                    LDSM_X4(b[nxt][0], b[nxt][1], b[nxt][2], b[nxt][3],
                            B_ADDR(0, k16 + 1));
                }
#pragma unroll
                for (int mi = 0; mi < 4; mi++) {
                    MMA_F16(acc[mi][nj * 2],     a[ka][mi][0], a[ka][mi][1],
                            a[ka][mi][2], a[ka][mi][3], b[cur][0], b[cur][1]);
                    MMA_F16(acc[mi][nj * 2 + 1], a[ka][mi][0], a[ka][mi][1],
                            a[ka][mi][2], a[ka][mi][3], b[cur][2], b[cur][3]);
                }
            }
        }
    }
#undef A_ADDR
#undef B_ADDR

    const int gid = lid >> 2, qid = lid & 3;
#pragma unroll
    for (int mi = 0; mi < 4; mi++) {
#pragma unroll
        for (int half = 0; half < 2; half++) {
            int m = m0 + wm * 64 + mi * 16 + gid + half * 8;
            if (m >= Mrows) continue;
            if (mode == 0) {
                int bb = m / N_, nn = m - bb * N_;
#pragma unroll
                for (int ni = 0; ni < 8; ni++) {
                    int col = n0 + wn * 64 + ni * 8 + qid * 2;
                    int which = col / INNER;
                    int inr = col - which * INNER;
                    int hh = inr >> 6, dd = inr & 63;
                    float mult = (which == 0) ? qscale[hh] * LOG2E : 1.0f;
                    __half* dst = ((which == 0) ? g_qh : (which == 1) ? g_kh : g_vh)
                                + ((((size_t)bb * H_ + hh) * N_ + nn) << 6) + dd;
                    *(__half2*)dst = __floats2half2_rn(acc[mi][ni][half * 2] * mult,
                                                       acc[mi][ni][half * 2 + 1] * mult);
                }
            } else {
                float* crow = Cout + (size_t)m * 768;
#pragma unroll
                for (int ni = 0; ni < 8; ni++) {
                    int col = n0 + wn * 64 + ni * 8 + qid * 2;
                    float2 bv = *(const float2*)(bias + col);
                    *(float2*)(crow + col) = make_float2(acc[mi][ni][half * 2] + bv.x,
                                                         acc[mi][ni][half * 2 + 1] + bv.y);
                }
            }
        }
    }
}

// ---------------- fused prologue: x->fp16 + two weight transposes --------------
#define NXB ((M_TOT * DIM_ / 4 + 255) / 256)        // 13854
#define NQB ((2304 / 32) * (768 / 32))              // 1728
#define NOB ((768 / 32) * (768 / 32))               // 576
__global__ __launch_bounds__(256) void prologue_fused(
    const float* __restrict__ x, __half* __restrict__ xh,
    const float* __restrict__ Wq, __half* __restrict__ Wqt,
    const float* __restrict__ Wo, __half* __restrict__ Wot)
{
    int blk = blockIdx.x;
    if (blk < NXB) {
        int i = blk * 256 + threadIdx.x;
        if (i < M_TOT * DIM_ / 4) {
            float4 v = ((const float4*)x)[i];
            ((__half2*)xh)[2 * i + 0] = __floats2half2_rn(v.x, v.y);
            ((__half2*)xh)[2 * i + 1] = __floats2half2_rn(v.z, v.w);
        }
        return;
    }
    __shared__ float tbuf[32][33];
    const float* W;  __half* Wt;  int rows, cols, bx, by;
    if (blk < NXB + NQB) {
        int t = blk - NXB;
        W = Wq; Wt = Wqt; rows = 768; cols = 2304;
        bx = t % 72; by = t / 72;
    } else {
        int t = blk - NXB - NQB;
        W = Wo; Wt = Wot; rows = 768; cols = 768;
        bx = t % 24; by = t / 24;
    }
    int tx = threadIdx.x & 31, ty8 = threadIdx.x >> 5;
#pragma unroll
    for (int r = ty8; r < 32; r += 8)
        tbuf[r][tx] = W[(size_t)(by * 32 + r) * cols + bx * 32 + tx];
    __syncthreads();
#pragma unroll
    for (int r = ty8; r < 32; r += 8)
        Wt[(size_t)(bx * 32 + r) * rows + by * 32 + tx] = __float2half(tbuf[tx][r]);
}

// ---------------- HMMA flash attention ------------------------------------------
// 128 q-rows x (b,h) per CTA, 8 warps (each owns 16 rows; per-thread state same
// as the 64-row version). Register-resident Q; log2-domain softmax; peeled tile 0;
// tiles 1..8 looped; 1-key tail. Halves K/V global traffic vs 64-row tiles.
// smem: Q 16KB | {K,V} x 2 bufs (16KB each) = 49152 B
__global__ __launch_bounds__(256) void attn_mma()
{
    extern __shared__ char smem[];
    const uint32_t sb = smem_to_u32(smem);
    const uint32_t sQ = sb;

    const int tid = threadIdx.x, wid = tid >> 5, lid = tid & 31;
    const int qt = blockIdx.x, h = blockIdx.y, b = blockIdx.z;
    const int q0 = qt * 128;
    const float NEG2 = NEG_MASK * LOG2E;
    const size_t hbase = (size_t)(b * H_ + h) * N_ * 64;
    const __half* Qg = g_qh + hbase;
    const __half* Kg = g_kh + hbase;
    const __half* Vg = g_vh + hbase;

    // Q tile 128x64 -> smem (zfill OOB rows): 1024 x 16B chunks, 256 thr x 4
#pragma unroll
    for (int i = 0; i < 4; i++) {
        int idx = tid + i * 256;
        int row = idx >> 3, cc = idx & 7;
        uint32_t off = row * 128 + cc * 16;
        uint32_t sw = off ^ ((off >> 3) & 0x70);
        const void* src = Qg + (size_t)(q0 + row) * 64 + cc * 8;
        int sz = (q0 + row < N_) ? 16 : 0;
        asm volatile("cp.async.cg.shared.global [%0], [%1], 16, %2;"
                     :: "r"(sQ + sw), "l"(src), "r"(sz));
    }
    asm volatile("cp.async.commit_group;");

    auto ldKV = [&](int kt) {
        uint32_t sK = sb + 16384 + (kt & 1) * 16384;
        uint32_t sV = sK + 8192;
        int k0 = kt * 64;
#pragma unroll
        for (int i = 0; i < 2; i++) {          // 512 chunks, 256 thr x 2
            int idx = tid + i * 256;
            int row = idx >> 3, cc = idx & 7;
            uint32_t off = row * 128 + cc * 16;
            uint32_t sw = off ^ ((off >> 3) & 0x70);
            int gj = k0 + row;
            int sz = (gj < N_) ? 16 : 0;
            const void* srcK = Kg + (size_t)gj * 64 + cc * 8;
            const void* srcV = Vg + (size_t)gj * 64 + cc * 8;
            asm volatile("cp.async.cg.shared.global [%0], [%1], 16, %2;"
                         :: "r"(sK + sw), "l"(srcK), "r"(sz));
            asm volatile("cp.async.cg.shared.global [%0], [%1], 16, %2;"
                         :: "r"(sV + sw), "l"(srcV), "r"(sz));
        }
        asm volatile("cp.async.commit_group;");
    };
    ldKV(0);

    // ---- Q fragments -> registers, once ----
    asm volatile("cp.async.wait_group 1;");
    __syncthreads();
    uint32_t qf[4][4];
#pragma unroll
    for (int k16 = 0; k16 < 4; k16++) {
        int row = wid * 16 + (lid & 15);
        uint32_t off = row * 128 + k16 * 32 + (lid >> 4) * 16;
        uint32_t sw = off ^ ((off >> 3) & 0x70);
        LDSM_X4(qf[k16][0], qf[k16][1], qf[k16][2], qf[k16][3], sQ + sw);
    }

    float m0r, m1r, l0r, l1r;
    float oacc[8][4];
#pragma unroll
    for (int nd = 0; nd < 8; nd++)
#pragma unroll
        for (int e = 0; e < 4; e++) oacc[nd][e] = 0.f;

    const int gi0 = q0 + wid * 16 + (lid >> 2);
    const int gi1 = gi0 + 8;
    const int cbx = (lid & 3) * 2;

    auto computeS = [&](uint32_t sK, float (*pv)[4]) {
#pragma unroll
        for (int ni = 0; ni < 8; ni++)
#pragma unroll
            for (int e = 0; e < 4; e++) pv[ni][e] = 0.f;
#pragma unroll
        for (int k16 = 0; k16 < 4; k16++) {
#pragma unroll
            for (int nj = 0; nj < 4; nj++) {
                int row = nj * 16 + ((lid >> 4) & 1) * 8 + (lid & 7);
                uint32_t off = row * 128 + k16 * 32 + ((lid >> 3) & 1) * 16;
                uint32_t sw = off ^ ((off >> 3) & 0x70);
                uint32_t r0, r1, r2, r3;
                LDSM_X4(r0, r1, r2, r3, sK + sw);
                MMA_F16(pv[nj * 2], qf[k16][0], qf[k16][1], qf[k16][2],
                        qf[k16][3], r0, r1);
                MMA_F16(pv[nj * 2 + 1], qf[k16][0], qf[k16][1], qf[k16][2],
                        qf[k16][3], r2, r3);
            }
        }
    };
    auto maskDiag = [&](int k0, float (*pv)[4]) {
#pragma unroll
        for (int ni = 0; ni < 8; ni++) {
#pragma unroll
            for (int e = 0; e < 4; e++) {
                int gj = k0 + ni * 8 + cbx + (e & 1);
                int gi = (e < 2) ? gi0 : gi1;
                if (gi == gj) pv[ni][e] = NEG2;
            }
        }
    };
    auto rowMax = [&](const float (*pv)[4], float& vmax0, float& vmax1) {
        vmax0 = -1e30f; vmax1 = -1e30f;
#pragma unroll
        for (int ni = 0; ni < 8; ni++) {
            vmax0 = fmaxf(vmax0, fmaxf(pv[ni][0], pv[ni][1]));
            vmax1 = fmaxf(vmax1, fmaxf(pv[ni][2], pv[ni][3]));
        }
        vmax0 = fmaxf(vmax0, __shfl_xor_sync(0xffffffffu, vmax0, 1));
        vmax0 = fmaxf(vmax0, __shfl_xor_sync(0xffffffffu, vmax0, 2));
        vmax1 = fmaxf(vmax1, __shfl_xor_sync(0xffffffffu, vmax1, 1));
        vmax1 = fmaxf(vmax1, __shfl_xor_sync(0xffffffffu, vmax1, 2));
    };
    auto expPack = [&](const float (*pv)[4], float mn0, float mn1,
                       uint32_t (*pf)[4], float& s0, float& s1) {
#pragma unroll
        for (int ni = 0; ni < 8; ni++) {
            float p0 = ex2f(pv[ni][0] - mn0);
            float p1 = ex2f(pv[ni][1] - mn0);
            float p2 = ex2f(pv[ni][2] - mn1);
            float p3 = ex2f(pv[ni][3] - mn1);
            s0 += p0 + p1;
            s1 += p2 + p3;
            pf[ni >> 1][(ni & 1) * 2 + 0] = pack_h2(p0, p1);
            pf[ni >> 1][(ni & 1) * 2 + 1] = pack_h2(p2, p3);
        }
    };
    auto pvMMA = [&](uint32_t sV, const uint32_t (*pf)[4]) {
#pragma unroll
        for (int ki = 0; ki < 4; ki++) {
#pragma unroll
            for (int di = 0; di < 4; di++) {
                int row = ki * 16 + (lid & 15);
                uint32_t off = row * 128 + di * 32 + (lid >> 4) * 16;
                uint32_t sw = off ^ ((off >> 3) & 0x70);
                uint32_t v0, v1, v2, v3;
                LDSM_X4_T(v0, v1, v2, v3, sV + sw);
                MMA_F16(oacc[di * 2],     pf[ki][0], pf[ki][1], pf[ki][2],
                        pf[ki][3], v0, v1);
                MMA_F16(oacc[di * 2 + 1], pf[ki][0], pf[ki][1], pf[ki][2],
                        pf[ki][3], v2, v3);
            }
        }
    };
    // does this CTA's q range [q0, q0+128) intersect key tile [k0, k0+64)?
    auto diagHit = [&](int k0) { return (k0 >= q0) && (k0 < q0 + 128); };

    // ---- PEELED tile 0 (no prior state: m=vmax, l=s, no rescale) ----
    {
        asm volatile("cp.async.wait_group 0;");
        __syncthreads();
        ldKV(1);
        const uint32_t sK = sb + 16384;        // buf 0
        const uint32_t sV = sK + 8192;

        float pv[8][4];
        computeS(sK, pv);
        if (diagHit(0)) maskDiag(0, pv);

        rowMax(pv, m0r, m1r);

        float s0 = 0.f, s1 = 0.f;
        uint32_t pf[4][4];
        expPack(pv, m0r, m1r, pf, s0, s1);
        s0 += __shfl_xor_sync(0xffffffffu, s0, 1);
        s0 += __shfl_xor_sync(0xffffffffu, s0, 2);
        s1 += __shfl_xor_sync(0xffffffffu, s1, 1);
        s1 += __shfl_xor_sync(0xffffffffu, s1, 2);
        l0r = s0; l1r = s1;
        pvMMA(sV, pf);
    }

    // ---- tiles 1..8 (full online-softmax updates) ----
    for (int kt = 1; kt < 9; kt++) {
        asm volatile("cp.async.wait_group 0;");
        __syncthreads();               // tile kt visible; buf (kt+1)&1 free
        ldKV(kt + 1);                  // kt+1 <= 9

        const uint32_t sK = sb + 16384 + (kt & 1) * 16384;
        const uint32_t sV = sK + 8192;
        const int k0 = kt * 64;

        float pv[8][4];
        computeS(sK, pv);
        if (diagHit(k0)) maskDiag(k0, pv);

        float vmax0, vmax1;
        rowMax(pv, vmax0, vmax1);

        float mn0 = fmaxf(m0r, vmax0), mn1 = fmaxf(m1r, vmax1);
        float cr0 = ex2f(m0r - mn0), cr1 = ex2f(m1r - mn1);
        m0r = mn0; m1r = mn1;

        float s0 = 0.f, s1 = 0.f;
        uint32_t pf[4][4];
        expPack(pv, mn0, mn1, pf, s0, s1);
        s0 += __shfl_xor_sync(0xffffffffu, s0, 1);
        s0 += __shfl_xor_sync(0xffffffffu, s0, 2);
        s1 += __shfl_xor_sync(0xffffffffu, s1, 1);
        s1 += __shfl_xor_sync(0xffffffffu, s1, 2);
        l0r = l0r * cr0 + s0;
        l1r = l1r * cr1 + s1;
#pragma unroll
        for (int nd = 0; nd < 8; nd++) {
            oacc[nd][0] *= cr0; oacc[nd][1] *= cr0;
            oacc[nd][2] *= cr1; oacc[nd][3] *= cr1;
        }

        pvMMA(sV, pf);
    }

    // ---- tail: tile 9, single valid key (576) ----
    {
        asm volatile("cp.async.wait_group 0;");
        __syncthreads();
        const uint32_t sK = sb + 16384 + 16384;   // buf (9&1)=1
        const uint32_t sV = sK + 8192;

        float st[4] = {0.f, 0.f, 0.f, 0.f};
#pragma unroll
        for (int k16 = 0; k16 < 4; k16++) {
            uint32_t r0, r1, r2, r3;
            int row = ((lid >> 4) & 1) * 8 + (lid & 7);
            uint32_t off = row * 128 + k16 * 32 + ((lid >> 3) & 1) * 16;
            uint32_t sw = off ^ ((off >> 3) & 0x70);
            LDSM_X4(r0, r1, r2, r3, sK + sw);
            MMA_F16(st, qf[k16][0], qf[k16][1], qf[k16][2], qf[k16][3], r0, r1);
        }

        float v0 = (cbx == 0) ? st[0] : -1e30f;   // row gi0, col 576
        float v1 = (cbx == 0) ? st[2] : -1e30f;   // row gi1
        if (gi0 == 576) v0 = NEG2;
        if (gi1 == 576) v1 = NEG2;

        float mx0 = v0, mx1 = v1;
        mx0 = fmaxf(mx0, __shfl_xor_sync(0xffffffffu, mx0, 1));
        mx0 = fmaxf(mx0, __shfl_xor_sync(0xffffffffu, mx0, 2));
        mx1 = fmaxf(mx1, __shfl_xor_sync(0xffffffffu, mx1, 1));
        mx1 = fmaxf(mx1, __shfl_xor_sync(0xffffffffu, mx1, 2));

        float mn0 = fmaxf(m0r, mx0), mn1 = fmaxf(m1r, mx1);
        float cr0 = ex2f(m0r - mn0), cr1 = ex2f(m1r - mn1);
        m0r = mn0; m1r = mn1;

        float p0 = ex2f(v0 - mn0), p1 = ex2f(v1 - mn1);
        float t0 = p0, t1 = p1;
        t0 += __shfl_xor_sync(0xffffffffu, t0, 1);
        t0 += __shfl_xor_sync(0xffffffffu, t0, 2);
        t1 += __shfl_xor_sync(0xffffffffu, t1, 1);
        t1 += __shfl_xor_sync(0xffffffffu, t1, 2);
        l0r = l0r * cr0 + t0;
        l1r = l1r * cr1 + t1;
#pragma unroll
        for (int nd = 0; nd < 8; nd++) {
            oacc[nd][0] *= cr0; oacc[nd][1] *= cr0;
            oacc[nd][2] *= cr1; oacc[nd][3] *= cr1;
        }

        uint32_t pa0 = pack_h2(p0, 0.f);
        uint32_t pa1 = pack_h2(p1, 0.f);
        uint32_t zz = 0u;
#pragma unroll
        for (int di = 0; di < 4; di++) {
            int row = (lid & 15);
            uint32_t off = row * 128 + di * 32 + (lid >> 4) * 16;
            uint32_t sw = off ^ ((off >> 3) & 0x70);
            uint32_t v0r, v1r, v2r, v3r;
            LDSM_X4_T(v0r, v1r, v2r, v3r, sV + sw);
            MMA_F16(oacc[di * 2],     pa0, pa1, zz, zz, v0r, v1r);
            MMA_F16(oacc[di * 2 + 1], pa0, pa1, zz, zz, v2r, v3r);
        }
    }

    float inv0 = 1.f / l0r, inv1 = 1.f / l1r;
    if (gi0 < N_) {
        __half* dst = g_atth + ((size_t)b * N_ + gi0) * INNER + h * 64 + cbx;
#pragma unroll
        for (int nd = 0; nd < 8; nd++)
            *(__half2*)(dst + nd * 8) = __floats2half2_rn(oacc[nd][0] * inv0,
                                                          oacc[nd][1] * inv0);
    }
    if (gi1 < N_) {
        __half* dst = g_atth + ((size_t)b * N_ + gi1) * INNER + h * 64 + cbx;
#pragma unroll
        for (int nd = 0; nd < 8; nd++)
            *(__half2*)(dst + nd * 8) = __floats2half2_rn(oacc[nd][2] * inv1,
                                                          oacc[nd][3] * inv1);
    }
}

// ---------------- launch --------------------------------------------------------
extern "C" void kernel_launch(void* const* d_in, const int* in_sizes, int n_in,
                              void* d_out, int out_size)
{
    const float* x      = (const float*)d_in[0];
    const float* W_qkv  = (const float*)d_in[1];
    const float* scale  = (const float*)d_in[2];
    const float* W_out  = (const float*)d_in[3];
    const float* b_out  = (const float*)d_in[4];
    float* out = (float*)d_out;
    (void)in_sizes; (void)n_in; (void)out_size;

    const int HGEMM_SMEM = 2 * 32768;           // 65536
    const int ATTN_SMEM  = 16384 + 2 * 16384;   // 49152
    cudaFuncSetAttribute(hgemm_mma, cudaFuncAttributeMaxDynamicSharedMemorySize,
                         HGEMM_SMEM);
    cudaFuncSetAttribute(attn_mma, cudaFuncAttributeMaxDynamicSharedMemorySize,
                         ATTN_SMEM);

    __half* xh;     cudaGetSymbolAddress((void**)&xh, g_xh);
    __half* atth;   cudaGetSymbolAddress((void**)&atth, g_atth);
    __half* wqkvt;  cudaGetSymbolAddress((void**)&wqkvt, g_wqkvt);
    __half* woutt;  cudaGetSymbolAddress((void**)&woutt, g_woutt);

    // 0) fused prologue: x -> fp16; W_qkv, W_out -> transposed fp16
    prologue_fused<<<NXB + NQB + NOB, 256>>>(x, xh, W_qkv, wqkvt, W_out, woutt);

    // 1) qkv projection (HMMA); q pre-scaled by scale[h]*log2e in epilogue
    hgemm_mma<<<dim3(2304 / 128, (M_TOT + 127) / 128), 128, HGEMM_SMEM>>>(
        xh, wqkvt, M_TOT, 0, nullptr, scale, nullptr);

    // 2) HMMA flash attention: 128-row q-tiles, 8 warps (halved K/V traffic)
    attn_mma<<<dim3((N_ + 127) / 128, H_, B_), 256, ATTN_SMEM>>>();

    // 3) output projection + bias (HMMA)
    hgemm_mma<<<dim3(768 / 128, (M_TOT + 127) / 128), 128, HGEMM_SMEM>>>(
        atth, woutt, M_TOT, 1, b_out, nullptr, out);
}

// round 16
// speedup vs baseline: 1.0652x; 1.0652x over previous
#include <cuda_runtime.h>
#include <cuda_fp16.h>
#include <cstdint>

#define B_    32
#define N_    577
#define H_    12
#define DH_   64
#define DIM_  768
#define INNER 768
#define M_TOT (B_ * N_)   // 18464
#define NEG_MASK (-987654321.0f)
#define LOG2E 1.4426950408889634f

// ---------------- scratch (device globals: no runtime allocation) -------------
__device__ __align__(128) __half g_qh[(size_t)B_ * H_ * N_ * DH_];   // pre-scaled by scale[h]*log2e
__device__ __align__(128) __half g_kh[(size_t)B_ * H_ * N_ * DH_];
__device__ __align__(128) __half g_vh[(size_t)B_ * H_ * N_ * DH_];
__device__ __align__(128) __half g_xh[(size_t)M_TOT * DIM_];
__device__ __align__(128) __half g_atth[(size_t)M_TOT * INNER];
__device__ __align__(128) __half g_wqkvt[(size_t)2304 * DIM_];
__device__ __align__(128) __half g_woutt[(size_t)DIM_ * INNER];

__device__ __forceinline__ uint32_t smem_to_u32(const void* p) {
    uint32_t a;
    asm("{ .reg .u64 t; cvta.to.shared.u64 t, %1; cvt.u32.u64 %0, t; }" : "=r"(a) : "l"(p));
    return a;
}
__device__ __forceinline__ float ex2f(float x) {
    float r;
    asm("ex2.approx.ftz.f32 %0, %1;" : "=f"(r) : "f"(x));
    return r;
}

#define MMA_F16(acc, a0, a1, a2, a3, b0, b1) \
    asm volatile("mma.sync.aligned.m16n8k16.row.col.f32.f16.f16.f32 " \
        "{%0,%1,%2,%3}, {%4,%5,%6,%7}, {%8,%9}, {%0,%1,%2,%3};" \
        : "+f"((acc)[0]), "+f"((acc)[1]), "+f"((acc)[2]), "+f"((acc)[3]) \
        : "r"(a0), "r"(a1), "r"(a2), "r"(a3), "r"(b0), "r"(b1))

#define LDSM_X4(r0, r1, r2, r3, addr) \
    asm volatile("ldmatrix.sync.aligned.m8n8.x4.shared.b16 {%0,%1,%2,%3}, [%4];" \
        : "=r"(r0), "=r"(r1), "=r"(r2), "=r"(r3) : "r"(addr))

#define LDSM_X4_T(r0, r1, r2, r3, addr) \
    asm volatile("ldmatrix.sync.aligned.m8n8.x4.trans.shared.b16 {%0,%1,%2,%3}, [%4];" \
        : "=r"(r0), "=r"(r1), "=r"(r2), "=r"(r3) : "r"(addr))

__device__ __forceinline__ uint32_t pack_h2(float lo, float hi) {
    __half2 h = __floats2half2_rn(lo, hi);
    return *(uint32_t*)&h;
}

// ---------------- HMMA GEMM (proven R10 best) -----------------------------------
__global__ __launch_bounds__(128, 2) void hgemm_mma(
    const __half* __restrict__ A, const __half* __restrict__ Bt,
    int Mrows, int mode, const float* __restrict__ bias,
    const float* __restrict__ qscale, float* __restrict__ Cout)
{
    extern __shared__ char smem[];
    const uint32_t sbase = smem_to_u32(smem);   // 2 bufs x (A 16K + B 16K)

    const int tid = threadIdx.x;
    const int wid = tid >> 5, lid = tid & 31;
    const int n0 = blockIdx.x * 128, m0 = blockIdx.y * 128;
    const int wm = wid >> 1, wn = wid & 1;

    float acc[4][8][4];
#pragma unroll
    for (int mi = 0; mi < 4; mi++)
#pragma unroll
        for (int ni = 0; ni < 8; ni++)
#pragma unroll
            for (int e = 0; e < 4; e++) acc[mi][ni][e] = 0.f;

    auto prefetch = [&](int c, int buf) {
        uint32_t sA = sbase + buf * 32768;
        uint32_t sB = sA + 16384;
#pragma unroll
        for (int i = 0; i < 8; i++) {
            int idx = tid + i * 128;
            int row = idx >> 3, cc = idx & 7;
            uint32_t off = row * 128 + cc * 16;
            uint32_t sw = off ^ ((off >> 3) & 0x70);
            const void* gA = A + (size_t)(m0 + row) * 768 + c * 64 + cc * 8;
            int szA = (m0 + row < Mrows) ? 16 : 0;
            asm volatile("cp.async.cg.shared.global [%0], [%1], 16, %2;"
                         :: "r"(sA + sw), "l"(gA), "r"(szA));
            const void* gB = Bt + (size_t)(n0 + row) * 768 + c * 64 + cc * 8;
            asm volatile("cp.async.cg.shared.global [%0], [%1], 16;"
                         :: "r"(sB + sw), "l"(gB));
        }
        asm volatile("cp.async.commit_group;");
    };

    uint32_t aOff[4], aXor[4], bOff[4], bXor[4];
#pragma unroll
    for (int mi = 0; mi < 4; mi++) {
        int row = wm * 64 + mi * 16 + (lid & 15);
        aOff[mi] = row * 128 + (lid >> 4) * 16;
        aXor[mi] = (aOff[mi] >> 3) & 0x70;
    }
#pragma unroll
    for (int nj = 0; nj < 4; nj++) {
        int row = wn * 64 + nj * 16 + ((lid >> 4) & 1) * 8 + (lid & 7);
        bOff[nj] = row * 128 + ((lid >> 3) & 1) * 16;
        bXor[nj] = (bOff[nj] >> 3) & 0x70;
    }
#define A_ADDR(mi, k) (sA + ((aOff[mi] + (k) * 32) ^ aXor[mi]))
#define B_ADDR(nj, k) (sB + ((bOff[nj] + (k) * 32) ^ bXor[nj]))

    prefetch(0, 0);

    for (int c = 0; c < 12; c++) {
        asm volatile("cp.async.wait_group 0;");
        __syncthreads();
        if (c < 11) prefetch(c + 1, (c + 1) & 1);

        const uint32_t sA = sbase + (c & 1) * 32768;
        const uint32_t sB = sA + 16384;

        uint32_t a[2][4][4], b[2][4];
#pragma unroll
        for (int mi = 0; mi < 4; mi++)
            LDSM_X4(a[0][mi][0], a[0][mi][1], a[0][mi][2], a[0][mi][3],
                    A_ADDR(mi, 0));
        LDSM_X4(b[0][0], b[0][1], b[0][2], b[0][3], B_ADDR(0, 0));

#pragma unroll
        for (int k16 = 0; k16 < 4; k16++) {
#pragma unroll
            for (int nj = 0; nj < 4; nj++) {
                const int cur = (k16 * 4 + nj) & 1, nxt = cur ^ 1;
                const int ka = k16 & 1;
                if (nj < 3) {
                    LDSM_X4(b[nxt][0], b[nxt][1], b[nxt][2], b[nxt][3],
                            B_ADDR(nj + 1, k16));
                } else if (k16 < 3) {
#pragma unroll
                    for (int mi = 0; mi < 4; mi++)
                        LDSM_X4(a[ka ^ 1][mi][0], a[ka ^ 1][mi][1],
                                a[ka ^ 1][mi][2], a[ka ^ 1][mi][3],
                                A_ADDR(mi, k16 + 1));
                    LDSM_X4(b[nxt][0], b[nxt][1], b[nxt][2], b[nxt][3],
                            B_ADDR(0, k16 + 1));
                }
#pragma unroll
                for (int mi = 0; mi < 4; mi++) {
                    MMA_F16(acc[mi][nj * 2],     a[ka][mi][0], a[ka][mi][1],
                            a[ka][mi][2], a[ka][mi][3], b[cur][0], b[cur][1]);
                    MMA_F16(acc[mi][nj * 2 + 1], a[ka][mi][0], a[ka][mi][1],
                            a[ka][mi][2], a[ka][mi][3], b[cur][2], b[cur][3]);
                }
            }
        }
    }
#undef A_ADDR
#undef B_ADDR

    const int gid = lid >> 2, qid = lid & 3;
#pragma unroll
    for (int mi = 0; mi < 4; mi++) {
#pragma unroll
        for (int half = 0; half < 2; half++) {
            int m = m0 + wm * 64 + mi * 16 + gid + half * 8;
            if (m >= Mrows) continue;
            if (mode == 0) {
                int bb = m / N_, nn = m - bb * N_;
#pragma unroll
                for (int ni = 0; ni < 8; ni++) {
                    int col = n0 + wn * 64 + ni * 8 + qid * 2;
                    int which = col / INNER;
                    int inr = col - which * INNER;
                    int hh = inr >> 6, dd = inr & 63;
                    float mult = (which == 0) ? qscale[hh] * LOG2E : 1.0f;
                    __half* dst = ((which == 0) ? g_qh : (which == 1) ? g_kh : g_vh)
                                + ((((size_t)bb * H_ + hh) * N_ + nn) << 6) + dd;
                    *(__half2*)dst = __floats2half2_rn(acc[mi][ni][half * 2] * mult,
                                                       acc[mi][ni][half * 2 + 1] * mult);
                }
            } else {
                float* crow = Cout + (size_t)m * 768;
#pragma unroll
                for (int ni = 0; ni < 8; ni++) {
                    int col = n0 + wn * 64 + ni * 8 + qid * 2;
                    float2 bv = *(const float2*)(bias + col);
                    *(float2*)(crow + col) = make_float2(acc[mi][ni][half * 2] + bv.x,
                                                         acc[mi][ni][half * 2 + 1] + bv.y);
                }
            }
        }
    }
}

// ---------------- fused prologue: x->fp16 + two weight transposes --------------
#define NXB ((M_TOT * DIM_ / 4 + 255) / 256)        // 13854
#define NQB ((2304 / 32) * (768 / 32))              // 1728
#define NOB ((768 / 32) * (768 / 32))               // 576
__global__ __launch_bounds__(256) void prologue_fused(
    const float* __restrict__ x, __half* __restrict__ xh,
    const float* __restrict__ Wq, __half* __restrict__ Wqt,
    const float* __restrict__ Wo, __half* __restrict__ Wot)
{
    int blk = blockIdx.x;
    if (blk < NXB) {
        int i = blk * 256 + threadIdx.x;
        if (i < M_TOT * DIM_ / 4) {
            float4 v = ((const float4*)x)[i];
            ((__half2*)xh)[2 * i + 0] = __floats2half2_rn(v.x, v.y);
            ((__half2*)xh)[2 * i + 1] = __floats2half2_rn(v.z, v.w);
        }
        return;
    }
    __shared__ float tbuf[32][33];
    const float* W;  __half* Wt;  int rows, cols, bx, by;
    if (blk < NXB + NQB) {
        int t = blk - NXB;
        W = Wq; Wt = Wqt; rows = 768; cols = 2304;
        bx = t % 72; by = t / 72;
    } else {
        int t = blk - NXB - NQB;
        W = Wo; Wt = Wot; rows = 768; cols = 768;
        bx = t % 24; by = t / 24;
    }
    int tx = threadIdx.x & 31, ty8 = threadIdx.x >> 5;
#pragma unroll
    for (int r = ty8; r < 32; r += 8)
        tbuf[r][tx] = W[(size_t)(by * 32 + r) * cols + bx * 32 + tx];
    __syncthreads();
#pragma unroll
    for (int r = ty8; r < 32; r += 8)
        Wt[(size_t)(bx * 32 + r) * rows + by * 32 + tx] = __float2half(tbuf[tx][r]);
}

// ---------------- HMMA flash attention (R10 best) -------------------------------
// 64 q-rows x (b,h) per CTA, 4 warps. Register-resident Q; log2-domain softmax
// (q pre-scaled by scale[h]*log2e); 9 full tiles + 1-key tail.
// smem: Q 8KB | {K,V} x 2 bufs (16KB each) = 40960 B
__global__ __launch_bounds__(128) void attn_mma()
{
    extern __shared__ char smem[];
    const uint32_t sb = smem_to_u32(smem);
    const uint32_t sQ = sb;

    const int tid = threadIdx.x, wid = tid >> 5, lid = tid & 31;
    const int qt = blockIdx.x, h = blockIdx.y, b = blockIdx.z;
    const int q0 = qt * 64;
    const float NEG2 = NEG_MASK * LOG2E;
    const size_t hbase = (size_t)(b * H_ + h) * N_ * 64;
    const __half* Qg = g_qh + hbase;
    const __half* Kg = g_kh + hbase;
    const __half* Vg = g_vh + hbase;

#pragma unroll
    for (int i = 0; i < 4; i++) {
        int idx = tid + i * 128;
        int row = idx >> 3, cc = idx & 7;
        uint32_t off = row * 128 + cc * 16;
        uint32_t sw = off ^ ((off >> 3) & 0x70);
        const void* src = Qg + (size_t)(q0 + row) * 64 + cc * 8;
        int sz = (q0 + row < N_) ? 16 : 0;
        asm volatile("cp.async.cg.shared.global [%0], [%1], 16, %2;"
                     :: "r"(sQ + sw), "l"(src), "r"(sz));
    }
    asm volatile("cp.async.commit_group;");

    auto ldKV = [&](int kt) {
        uint32_t sK = sb + 8192 + (kt & 1) * 16384;
        uint32_t sV = sK + 8192;
        int k0 = kt * 64;
#pragma unroll
        for (int i = 0; i < 4; i++) {
            int idx = tid + i * 128;
            int row = idx >> 3, cc = idx & 7;
            uint32_t off = row * 128 + cc * 16;
            uint32_t sw = off ^ ((off >> 3) & 0x70);
            int gj = k0 + row;
            int sz = (gj < N_) ? 16 : 0;
            const void* srcK = Kg + (size_t)gj * 64 + cc * 8;
            const void* srcV = Vg + (size_t)gj * 64 + cc * 8;
            asm volatile("cp.async.cg.shared.global [%0], [%1], 16, %2;"
                         :: "r"(sK + sw), "l"(srcK), "r"(sz));
            asm volatile("cp.async.cg.shared.global [%0], [%1], 16, %2;"
                         :: "r"(sV + sw), "l"(srcV), "r"(sz));
        }
        asm volatile("cp.async.commit_group;");
    };
    ldKV(0);

    // ---- Q fragments -> registers, once (wait only on the Q copy group) ----
    asm volatile("cp.async.wait_group 1;");
    __syncthreads();
    uint32_t qf[4][4];
#pragma unroll
    for (int k16 = 0; k16 < 4; k16++) {
        int row = wid * 16 + (lid & 15);
        uint32_t off = row * 128 + k16 * 32 + (lid >> 4) * 16;
        uint32_t sw = off ^ ((off >> 3) & 0x70);
        LDSM_X4(qf[k16][0], qf[k16][1], qf[k16][2], qf[k16][3], sQ + sw);
    }

    float m0r = -1e30f, m1r = -1e30f, l0r = 0.f, l1r = 0.f;
    float oacc[8][4];
#pragma unroll
    for (int nd = 0; nd < 8; nd++)
#pragma unroll
        for (int e = 0; e < 4; e++) oacc[nd][e] = 0.f;

    const int gi0 = q0 + wid * 16 + (lid >> 2);
    const int gi1 = gi0 + 8;
    const int cbx = (lid & 3) * 2;

    // ---- main loop: 9 full tiles, keys 0..575 (all valid) ----
    for (int kt = 0; kt < 9; kt++) {
        asm volatile("cp.async.wait_group 0;");
        __syncthreads();               // tile kt visible; buf (kt+1)&1 free
        ldKV(kt + 1);                  // kt+1 <= 9

        const uint32_t sK = sb + 8192 + (kt & 1) * 16384;
        const uint32_t sV = sK + 8192;
        const int k0 = kt * 64;

        float pv[8][4];
#pragma unroll
        for (int ni = 0; ni < 8; ni++)
#pragma unroll
            for (int e = 0; e < 4; e++) pv[ni][e] = 0.f;

#pragma unroll
        for (int k16 = 0; k16 < 4; k16++) {
#pragma unroll
            for (int nj = 0; nj < 4; nj++) {
                int row = nj * 16 + ((lid >> 4) & 1) * 8 + (lid & 7);
                uint32_t off = row * 128 + k16 * 32 + ((lid >> 3) & 1) * 16;
                uint32_t sw = off ^ ((off >> 3) & 0x70);
                uint32_t r0, r1, r2, r3;
                LDSM_X4(r0, r1, r2, r3, sK + sw);
                MMA_F16(pv[nj * 2], qf[k16][0], qf[k16][1], qf[k16][2], qf[k16][3], r0, r1);
                MMA_F16(pv[nj * 2 + 1], qf[k16][0], qf[k16][1], qf[k16][2], qf[k16][3], r2, r3);
            }
        }

        // ---- diag mask (only on the diagonal tile); S already log2-scaled ----
        if (k0 == q0) {
#pragma unroll
            for (int ni = 0; ni < 8; ni++) {
#pragma unroll
                for (int e = 0; e < 4; e++) {
                    int gj = k0 + ni * 8 + cbx + (e & 1);
                    int gi = (e < 2) ? gi0 : gi1;
                    if (gi == gj) pv[ni][e] = NEG2;
                }
            }
        }

        float vmax0 = -1e30f, vmax1 = -1e30f;
#pragma unroll
        for (int ni = 0; ni < 8; ni++) {
            vmax0 = fmaxf(vmax0, fmaxf(pv[ni][0], pv[ni][1]));
            vmax1 = fmaxf(vmax1, fmaxf(pv[ni][2], pv[ni][3]));
        }
        vmax0 = fmaxf(vmax0, __shfl_xor_sync(0xffffffffu, vmax0, 1));
        vmax0 = fmaxf(vmax0, __shfl_xor_sync(0xffffffffu, vmax0, 2));
        vmax1 = fmaxf(vmax1, __shfl_xor_sync(0xffffffffu, vmax1, 1));
        vmax1 = fmaxf(vmax1, __shfl_xor_sync(0xffffffffu, vmax1, 2));

        float mn0 = fmaxf(m0r, vmax0), mn1 = fmaxf(m1r, vmax1);
        float cr0 = ex2f(m0r - mn0), cr1 = ex2f(m1r - mn1);
        m0r = mn0; m1r = mn1;

        float s0 = 0.f, s1 = 0.f;
        uint32_t pf[4][4];
#pragma unroll
        for (int ni = 0; ni < 8; ni++) {
            float p0 = ex2f(pv[ni][0] - mn0);
            float p1 = ex2f(pv[ni][1] - mn0);
            float p2 = ex2f(pv[ni][2] - mn1);
            float p3 = ex2f(pv[ni][3] - mn1);
            s0 += p0 + p1;
            s1 += p2 + p3;
            pf[ni >> 1][(ni & 1) * 2 + 0] = pack_h2(p0, p1);
            pf[ni >> 1][(ni & 1) * 2 + 1] = pack_h2(p2, p3);
        }
        s0 += __shfl_xor_sync(0xffffffffu, s0, 1);
        s0 += __shfl_xor_sync(0xffffffffu, s0, 2);
        s1 += __shfl_xor_sync(0xffffffffu, s1, 1);
        s1 += __shfl_xor_sync(0xffffffffu, s1, 2);
        l0r = l0r * cr0 + s0;
        l1r = l1r * cr1 + s1;
#pragma unroll
        for (int nd = 0; nd < 8; nd++) {
            oacc[nd][0] *= cr0; oacc[nd][1] *= cr0;
            oacc[nd][2] *= cr1; oacc[nd][3] *= cr1;
        }

#pragma unroll
        for (int ki = 0; ki < 4; ki++) {
#pragma unroll
            for (int di = 0; di < 4; di++) {
                int row = ki * 16 + (lid & 15);
                uint32_t off = row * 128 + di * 32 + (lid >> 4) * 16;
                uint32_t sw = off ^ ((off >> 3) & 0x70);
                uint32_t v0, v1, v2, v3;
                LDSM_X4_T(v0, v1, v2, v3, sV + sw);
                MMA_F16(oacc[di * 2],     pf[ki][0], pf[ki][1], pf[ki][2], pf[ki][3], v0, v1);
                MMA_F16(oacc[di * 2 + 1], pf[ki][0], pf[ki][1], pf[ki][2], pf[ki][3], v2, v3);
            }
        }
    }

    // ---- tail: tile 9, single valid key (576) ----
    {
        asm volatile("cp.async.wait_group 0;");
        __syncthreads();
        const uint32_t sK = sb + 8192 + 16384;   // buf (9&1)=1
        const uint32_t sV = sK + 8192;

        float st[4] = {0.f, 0.f, 0.f, 0.f};
#pragma unroll
        for (int k16 = 0; k16 < 4; k16++) {
            uint32_t r0, r1, r2, r3;
            int row = ((lid >> 4) & 1) * 8 + (lid & 7);
            uint32_t off = row * 128 + k16 * 32 + ((lid >> 3) & 1) * 16;
            uint32_t sw = off ^ ((off >> 3) & 0x70);
            LDSM_X4(r0, r1, r2, r3, sK + sw);
            MMA_F16(st, qf[k16][0], qf[k16][1], qf[k16][2], qf[k16][3], r0, r1);
        }

        float v0 = (cbx == 0) ? st[0] : -1e30f;   // row gi0, col 576
        float v1 = (cbx == 0) ? st[2] : -1e30f;   // row gi1
        if (gi0 == 576) v0 = NEG2;
        if (gi1 == 576) v1 = NEG2;

        float mx0 = v0, mx1 = v1;
        mx0 = fmaxf(mx0, __shfl_xor_sync(0xffffffffu, mx0, 1));
        mx0 = fmaxf(mx0, __shfl_xor_sync(0xffffffffu, mx0, 2));
        mx1 = fmaxf(mx1, __shfl_xor_sync(0xffffffffu, mx1, 1));
        mx1 = fmaxf(mx1, __shfl_xor_sync(0xffffffffu, mx1, 2));

        float mn0 = fmaxf(m0r, mx0), mn1 = fmaxf(m1r, mx1);
        float cr0 = ex2f(m0r - mn0), cr1 = ex2f(m1r - mn1);
        m0r = mn0; m1r = mn1;

        float p0 = ex2f(v0 - mn0), p1 = ex2f(v1 - mn1);
        float t0 = p0, t1 = p1;
        t0 += __shfl_xor_sync(0xffffffffu, t0, 1);
        t0 += __shfl_xor_sync(0xffffffffu, t0, 2);
        t1 += __shfl_xor_sync(0xffffffffu, t1, 1);
        t1 += __shfl_xor_sync(0xffffffffu, t1, 2);
        l0r = l0r * cr0 + t0;
        l1r = l1r * cr1 + t1;
#pragma unroll
        for (int nd = 0; nd < 8; nd++) {
            oacc[nd][0] *= cr0; oacc[nd][1] *= cr0;
            oacc[nd][2] *= cr1; oacc[nd][3] *= cr1;
        }

        uint32_t pa0 = pack_h2(p0, 0.f);
        uint32_t pa1 = pack_h2(p1, 0.f);
        uint32_t zz = 0u;
#pragma unroll
        for (int di = 0; di < 4; di++) {
            int row = (lid & 15);
            uint32_t off = row * 128 + di * 32 + (lid >> 4) * 16;
            uint32_t sw = off ^ ((off >> 3) & 0x70);
            uint32_t v0r, v1r, v2r, v3r;
            LDSM_X4_T(v0r, v1r, v2r, v3r, sV + sw);
            MMA_F16(oacc[di * 2],     pa0, pa1, zz, zz, v0r, v1r);
            MMA_F16(oacc[di * 2 + 1], pa0, pa1, zz, zz, v2r, v3r);
        }
    }

    float inv0 = 1.f / l0r, inv1 = 1.f / l1r;
    if (gi0 < N_) {
        __half* dst = g_atth + ((size_t)b * N_ + gi0) * INNER + h * 64 + cbx;
#pragma unroll
        for (int nd = 0; nd < 8; nd++)
            *(__half2*)(dst + nd * 8) = __floats2half2_rn(oacc[nd][0] * inv0,
                                                          oacc[nd][1] * inv0);
    }
    if (gi1 < N_) {
        __half* dst = g_atth + ((size_t)b * N_ + gi1) * INNER + h * 64 + cbx;
#pragma unroll
        for (int nd = 0; nd < 8; nd++)
            *(__half2*)(dst + nd * 8) = __floats2half2_rn(oacc[nd][2] * inv1,
                                                          oacc[nd][3] * inv1);
    }
}

// ---------------- launch --------------------------------------------------------
extern "C" void kernel_launch(void* const* d_in, const int* in_sizes, int n_in,
                              void* d_out, int out_size)
{
    const float* x      = (const float*)d_in[0];
    const float* W_qkv  = (const float*)d_in[1];
    const float* scale  = (const float*)d_in[2];
    const float* W_out  = (const float*)d_in[3];
    const float* b_out  = (const float*)d_in[4];
    float* out = (float*)d_out;
    (void)in_sizes; (void)n_in; (void)out_size;

    const int HGEMM_SMEM = 2 * 32768;          // 65536
    const int ATTN_SMEM  = 8192 + 2 * 16384;   // 40960
    cudaFuncSetAttribute(hgemm_mma, cudaFuncAttributeMaxDynamicSharedMemorySize,
                         HGEMM_SMEM);
    cudaFuncSetAttribute(attn_mma, cudaFuncAttributeMaxDynamicSharedMemorySize,
                         ATTN_SMEM);

    __half* xh;     cudaGetSymbolAddress((void**)&xh, g_xh);
    __half* atth;   cudaGetSymbolAddress((void**)&atth, g_atth);
    __half* wqkvt;  cudaGetSymbolAddress((void**)&wqkvt, g_wqkvt);
    __half* woutt;  cudaGetSymbolAddress((void**)&woutt, g_woutt);

    // 0) fused prologue: x -> fp16; W_qkv, W_out -> transposed fp16
    prologue_fused<<<NXB + NQB + NOB, 256>>>(x, xh, W_qkv, wqkvt, W_out, woutt);

    // 1) qkv projection (HMMA); q pre-scaled by scale[h]*log2e in epilogue
    hgemm_mma<<<dim3(2304 / 128, (M_TOT + 127) / 128), 128, HGEMM_SMEM>>>(
        xh, wqkvt, M_TOT, 0, nullptr, scale, nullptr);

    // 2) HMMA flash attention (log2-domain softmax, 64-row q-tiles)
    attn_mma<<<dim3((N_ + 63) / 64, H_, B_), 128, ATTN_SMEM>>>();

    // 3) output projection + bias (HMMA)
    hgemm_mma<<<dim3(768 / 128, (M_TOT + 127) / 128), 128, HGEMM_SMEM>>>(
        atth, woutt, M_TOT, 1, b_out, nullptr, out);
}

// round 17
// speedup vs baseline: 1.0664x; 1.0011x over previous
#include <cuda_runtime.h>
#include <cuda_fp16.h>
#include <cstdint>

#define B_    32
#define N_    577
#define H_    12
#define DH_   64
#define DIM_  768
#define INNER 768
#define M_TOT (B_ * N_)   // 18464
#define NEG_MASK (-987654321.0f)
#define LOG2E 1.4426950408889634f

// ---------------- scratch (device globals: no runtime allocation) -------------
__device__ __align__(128) __half g_qh[(size_t)B_ * H_ * N_ * DH_];   // pre-scaled by scale[h]*log2e
__device__ __align__(128) __half g_kh[(size_t)B_ * H_ * N_ * DH_];
__device__ __align__(128) __half g_vh[(size_t)B_ * H_ * N_ * DH_];
__device__ __align__(128) __half g_xh[(size_t)M_TOT * DIM_];
__device__ __align__(128) __half g_atth[(size_t)M_TOT * INNER];
__device__ __align__(128) __half g_wqkvt[(size_t)2304 * DIM_];
__device__ __align__(128) __half g_woutt[(size_t)DIM_ * INNER];

__device__ __forceinline__ uint32_t smem_to_u32(const void* p) {
    uint32_t a;
    asm("{ .reg .u64 t; cvta.to.shared.u64 t, %1; cvt.u32.u64 %0, t; }" : "=r"(a) : "l"(p));
    return a;
}
__device__ __forceinline__ float ex2f(float x) {
    float r;
    asm("ex2.approx.ftz.f32 %0, %1;" : "=f"(r) : "f"(x));
    return r;
}

#define MMA_F16(acc, a0, a1, a2, a3, b0, b1) \
    asm volatile("mma.sync.aligned.m16n8k16.row.col.f32.f16.f16.f32 " \
        "{%0,%1,%2,%3}, {%4,%5,%6,%7}, {%8,%9}, {%0,%1,%2,%3};" \
        : "+f"((acc)[0]), "+f"((acc)[1]), "+f"((acc)[2]), "+f"((acc)[3]) \
        : "r"(a0), "r"(a1), "r"(a2), "r"(a3), "r"(b0), "r"(b1))

#define LDSM_X4(r0, r1, r2, r3, addr) \
    asm volatile("ldmatrix.sync.aligned.m8n8.x4.shared.b16 {%0,%1,%2,%3}, [%4];" \
        : "=r"(r0), "=r"(r1), "=r"(r2), "=r"(r3) : "r"(addr))

#define LDSM_X4_T(r0, r1, r2, r3, addr) \
    asm volatile("ldmatrix.sync.aligned.m8n8.x4.trans.shared.b16 {%0,%1,%2,%3}, [%4];" \
        : "=r"(r0), "=r"(r1), "=r"(r2), "=r"(r3) : "r"(addr))

__device__ __forceinline__ uint32_t pack_h2(float lo, float hi) {
    __half2 h = __floats2half2_rn(lo, hi);
    return *(uint32_t*)&h;
}

// ---------------- HMMA GEMM (proven R10 best) -----------------------------------
__global__ __launch_bounds__(128, 2) void hgemm_mma(
    const __half* __restrict__ A, const __half* __restrict__ Bt,
    int Mrows, int mode, const float* __restrict__ bias,
    const float* __restrict__ qscale, float* __restrict__ Cout)
{
    extern __shared__ char smem[];
    const uint32_t sbase = smem_to_u32(smem);   // 2 bufs x (A 16K + B 16K)

    const int tid = threadIdx.x;
    const int wid = tid >> 5, lid = tid & 31;
    const int n0 = blockIdx.x * 128, m0 = blockIdx.y * 128;
    const int wm = wid >> 1, wn = wid & 1;

    float acc[4][8][4];
#pragma unroll
    for (int mi = 0; mi < 4; mi++)
#pragma unroll
        for (int ni = 0; ni < 8; ni++)
#pragma unroll
            for (int e = 0; e < 4; e++) acc[mi][ni][e] = 0.f;

    auto prefetch = [&](int c, int buf) {
        uint32_t sA = sbase + buf * 32768;
        uint32_t sB = sA + 16384;
#pragma unroll
        for (int i = 0; i < 8; i++) {
            int idx = tid + i * 128;
            int row = idx >> 3, cc = idx & 7;
            uint32_t off = row * 128 + cc * 16;
            uint32_t sw = off ^ ((off >> 3) & 0x70);
            const void* gA = A + (size_t)(m0 + row) * 768 + c * 64 + cc * 8;
            int szA = (m0 + row < Mrows) ? 16 : 0;
            asm volatile("cp.async.cg.shared.global [%0], [%1], 16, %2;"
                         :: "r"(sA + sw), "l"(gA), "r"(szA));
            const void* gB = Bt + (size_t)(n0 + row) * 768 + c * 64 + cc * 8;
            asm volatile("cp.async.cg.shared.global [%0], [%1], 16;"
                         :: "r"(sB + sw), "l"(gB));
        }
        asm volatile("cp.async.commit_group;");
    };

    uint32_t aOff[4], aXor[4], bOff[4], bXor[4];
#pragma unroll
    for (int mi = 0; mi < 4; mi++) {
        int row = wm * 64 + mi * 16 + (lid & 15);
        aOff[mi] = row * 128 + (lid >> 4) * 16;
        aXor[mi] = (aOff[mi] >> 3) & 0x70;
    }
#pragma unroll
    for (int nj = 0; nj < 4; nj++) {
        int row = wn * 64 + nj * 16 + ((lid >> 4) & 1) * 8 + (lid & 7);
        bOff[nj] = row * 128 + ((lid >> 3) & 1) * 16;
        bXor[nj] = (bOff[nj] >> 3) & 0x70;
    }
#define A_ADDR(mi, k) (sA + ((aOff[mi] + (k) * 32) ^ aXor[mi]))
#define B_ADDR(nj, k) (sB + ((bOff[nj] + (k) * 32) ^ bXor[nj]))

    prefetch(0, 0);

    for (int c = 0; c < 12; c++) {
        asm volatile("cp.async.wait_group 0;");
        __syncthreads();
        if (c < 11) prefetch(c + 1, (c + 1) & 1);

        const uint32_t sA = sbase + (c & 1) * 32768;
        const uint32_t sB = sA + 16384;

        uint32_t a[2][4][4], b[2][4];
#pragma unroll
        for (int mi = 0; mi < 4; mi++)
            LDSM_X4(a[0][mi][0], a[0][mi][1], a[0][mi][2], a[0][mi][3],
                    A_ADDR(mi, 0));
        LDSM_X4(b[0][0], b[0][1], b[0][2], b[0][3], B_ADDR(0, 0));

#pragma unroll
        for (int k16 = 0; k16 < 4; k16++) {
#pragma unroll
            for (int nj = 0; nj < 4; nj++) {
                const int cur = (k16 * 4 + nj) & 1, nxt = cur ^ 1;
                const int ka = k16 & 1;
                if (nj < 3) {
                    LDSM_X4(b[nxt][0], b[nxt][1], b[nxt][2], b[nxt][3],
                            B_ADDR(nj + 1, k16));
                } else if (k16 < 3) {
#pragma unroll
                    for (int mi = 0; mi < 4; mi++)
                        LDSM_X4(a[ka ^ 1][mi][0], a[ka ^ 1][mi][1],
                                a[ka ^ 1][mi][2], a[ka ^ 1][mi][3],
                                A_ADDR(mi, k16 + 1));
                    LDSM_X4(b[nxt][0], b[nxt][1], b[nxt][2], b[nxt][3],
                            B_ADDR(0, k16 + 1));
                }
#pragma unroll
                for (int mi = 0; mi < 4; mi++) {
                    MMA_F16(acc[mi][nj * 2],     a[ka][mi][0], a[ka][mi][1],
                            a[ka][mi][2], a[ka][mi][3], b[cur][0], b[cur][1]);
                    MMA_F16(acc[mi][nj * 2 + 1], a[ka][mi][0], a[ka][mi][1],
                            a[ka][mi][2], a[ka][mi][3], b[cur][2], b[cur][3]);
                }
            }
        }
    }
#undef A_ADDR
#undef B_ADDR

    const int gid = lid >> 2, qid = lid & 3;
#pragma unroll
    for (int mi = 0; mi < 4; mi++) {
#pragma unroll
        for (int half = 0; half < 2; half++) {
            int m = m0 + wm * 64 + mi * 16 + gid + half * 8;
            if (m >= Mrows) continue;
            if (mode == 0) {
                int bb = m / N_, nn = m - bb * N_;
#pragma unroll
                for (int ni = 0; ni < 8; ni++) {
                    int col = n0 + wn * 64 + ni * 8 + qid * 2;
                    int which = col / INNER;
                    int inr = col - which * INNER;
                    int hh = inr >> 6, dd = inr & 63;
                    float mult = (which == 0) ? qscale[hh] * LOG2E : 1.0f;
                    __half* dst = ((which == 0) ? g_qh : (which == 1) ? g_kh : g_vh)
                                + ((((size_t)bb * H_ + hh) * N_ + nn) << 6) + dd;
                    *(__half2*)dst = __floats2half2_rn(acc[mi][ni][half * 2] * mult,
                                                       acc[mi][ni][half * 2 + 1] * mult);
                }
            } else {
                float* crow = Cout + (size_t)m * 768;
#pragma unroll
                for (int ni = 0; ni < 8; ni++) {
                    int col = n0 + wn * 64 + ni * 8 + qid * 2;
                    float2 bv = *(const float2*)(bias + col);
                    *(float2*)(crow + col) = make_float2(acc[mi][ni][half * 2] + bv.x,
                                                         acc[mi][ni][half * 2 + 1] + bv.y);
                }
            }
        }
    }
}

// ---------------- fused prologue: x->fp16 + two weight transposes --------------
#define NXB ((M_TOT * DIM_ / 4 + 255) / 256)        // 13854
#define NQB ((2304 / 32) * (768 / 32))              // 1728
#define NOB ((768 / 32) * (768 / 32))               // 576
__global__ __launch_bounds__(256) void prologue_fused(
    const float* __restrict__ x, __half* __restrict__ xh,
    const float* __restrict__ Wq, __half* __restrict__ Wqt,
    const float* __restrict__ Wo, __half* __restrict__ Wot)
{
    int blk = blockIdx.x;
    if (blk < NXB) {
        int i = blk * 256 + threadIdx.x;
        if (i < M_TOT * DIM_ / 4) {
            float4 v = ((const float4*)x)[i];
            ((__half2*)xh)[2 * i + 0] = __floats2half2_rn(v.x, v.y);
            ((__half2*)xh)[2 * i + 1] = __floats2half2_rn(v.z, v.w);
        }
        return;
    }
    __shared__ float tbuf[32][33];
    const float* W;  __half* Wt;  int rows, cols, bx, by;
    if (blk < NXB + NQB) {
        int t = blk - NXB;
        W = Wq; Wt = Wqt; rows = 768; cols = 2304;
        bx = t % 72; by = t / 72;
    } else {
        int t = blk - NXB - NQB;
        W = Wo; Wt = Wot; rows = 768; cols = 768;
        bx = t % 24; by = t / 24;
    }
    int tx = threadIdx.x & 31, ty8 = threadIdx.x >> 5;
#pragma unroll
    for (int r = ty8; r < 32; r += 8)
        tbuf[r][tx] = W[(size_t)(by * 32 + r) * cols + bx * 32 + tx];
    __syncthreads();
#pragma unroll
    for (int r = ty8; r < 32; r += 8)
        Wt[(size_t)(bx * 32 + r) * rows + by * 32 + tx] = __float2half(tbuf[tx][r]);
}

// ---------------- HMMA flash attention ------------------------------------------
// 64 q-rows x (b,h) per CTA, 4 warps. Register-resident Q; log2-domain softmax
// (q pre-scaled by scale[h]*log2e). Tiles 0..7 looped; FINAL EPOCH fuses tile 8
// with the 1-key tail (key 576): one softmax state update for 65 keys.
// smem: Q 8KB | {K,V} x 2 bufs (16KB each) = 40960 B
__global__ __launch_bounds__(128) void attn_mma()
{
    extern __shared__ char smem[];
    const uint32_t sb = smem_to_u32(smem);
    const uint32_t sQ = sb;

    const int tid = threadIdx.x, wid = tid >> 5, lid = tid & 31;
    const int qt = blockIdx.x, h = blockIdx.y, b = blockIdx.z;
    const int q0 = qt * 64;
    const float NEG2 = NEG_MASK * LOG2E;
    const size_t hbase = (size_t)(b * H_ + h) * N_ * 64;
    const __half* Qg = g_qh + hbase;
    const __half* Kg = g_kh + hbase;
    const __half* Vg = g_vh + hbase;

#pragma unroll
    for (int i = 0; i < 4; i++) {
        int idx = tid + i * 128;
        int row = idx >> 3, cc = idx & 7;
        uint32_t off = row * 128 + cc * 16;
        uint32_t sw = off ^ ((off >> 3) & 0x70);
        const void* src = Qg + (size_t)(q0 + row) * 64 + cc * 8;
        int sz = (q0 + row < N_) ? 16 : 0;
        asm volatile("cp.async.cg.shared.global [%0], [%1], 16, %2;"
                     :: "r"(sQ + sw), "l"(src), "r"(sz));
    }
    asm volatile("cp.async.commit_group;");

    auto ldKV = [&](int kt) {
        uint32_t sK = sb + 8192 + (kt & 1) * 16384;
        uint32_t sV = sK + 8192;
        int k0 = kt * 64;
#pragma unroll
        for (int i = 0; i < 4; i++) {
            int idx = tid + i * 128;
            int row = idx >> 3, cc = idx & 7;
            uint32_t off = row * 128 + cc * 16;
            uint32_t sw = off ^ ((off >> 3) & 0x70);
            int gj = k0 + row;
            int sz = (gj < N_) ? 16 : 0;
            const void* srcK = Kg + (size_t)gj * 64 + cc * 8;
            const void* srcV = Vg + (size_t)gj * 64 + cc * 8;
            asm volatile("cp.async.cg.shared.global [%0], [%1], 16, %2;"
                         :: "r"(sK + sw), "l"(srcK), "r"(sz));
            asm volatile("cp.async.cg.shared.global [%0], [%1], 16, %2;"
                         :: "r"(sV + sw), "l"(srcV), "r"(sz));
        }
        asm volatile("cp.async.commit_group;");
    };
    ldKV(0);

    // ---- Q fragments -> registers, once ----
    asm volatile("cp.async.wait_group 1;");
    __syncthreads();
    uint32_t qf[4][4];
#pragma unroll
    for (int k16 = 0; k16 < 4; k16++) {
        int row = wid * 16 + (lid & 15);
        uint32_t off = row * 128 + k16 * 32 + (lid >> 4) * 16;
        uint32_t sw = off ^ ((off >> 3) & 0x70);
        LDSM_X4(qf[k16][0], qf[k16][1], qf[k16][2], qf[k16][3], sQ + sw);
    }

    float m0r = -1e30f, m1r = -1e30f, l0r = 0.f, l1r = 0.f;
    float oacc[8][4];
#pragma unroll
    for (int nd = 0; nd < 8; nd++)
#pragma unroll
        for (int e = 0; e < 4; e++) oacc[nd][e] = 0.f;

    const int gi0 = q0 + wid * 16 + (lid >> 2);
    const int gi1 = gi0 + 8;
    const int cbx = (lid & 3) * 2;

    auto computeS = [&](uint32_t sK, float (*pv)[4]) {
#pragma unroll
        for (int ni = 0; ni < 8; ni++)
#pragma unroll
            for (int e = 0; e < 4; e++) pv[ni][e] = 0.f;
#pragma unroll
        for (int k16 = 0; k16 < 4; k16++) {
#pragma unroll
            for (int nj = 0; nj < 4; nj++) {
                int row = nj * 16 + ((lid >> 4) & 1) * 8 + (lid & 7);
                uint32_t off = row * 128 + k16 * 32 + ((lid >> 3) & 1) * 16;
                uint32_t sw = off ^ ((off >> 3) & 0x70);
                uint32_t r0, r1, r2, r3;
                LDSM_X4(r0, r1, r2, r3, sK + sw);
                MMA_F16(pv[nj * 2], qf[k16][0], qf[k16][1], qf[k16][2],
                        qf[k16][3], r0, r1);
                MMA_F16(pv[nj * 2 + 1], qf[k16][0], qf[k16][1], qf[k16][2],
                        qf[k16][3], r2, r3);
            }
        }
    };
    auto maskDiag = [&](int k0, float (*pv)[4]) {
#pragma unroll
        for (int ni = 0; ni < 8; ni++) {
#pragma unroll
            for (int e = 0; e < 4; e++) {
                int gj = k0 + ni * 8 + cbx + (e & 1);
                int gi = (e < 2) ? gi0 : gi1;
                if (gi == gj) pv[ni][e] = NEG2;
            }
        }
    };
    auto pvMMA = [&](uint32_t sV, const uint32_t (*pf)[4]) {
#pragma unroll
        for (int ki = 0; ki < 4; ki++) {
#pragma unroll
            for (int di = 0; di < 4; di++) {
                int row = ki * 16 + (lid & 15);
                uint32_t off = row * 128 + di * 32 + (lid >> 4) * 16;
                uint32_t sw = off ^ ((off >> 3) & 0x70);
                uint32_t v0, v1, v2, v3;
                LDSM_X4_T(v0, v1, v2, v3, sV + sw);
                MMA_F16(oacc[di * 2],     pf[ki][0], pf[ki][1], pf[ki][2],
                        pf[ki][3], v0, v1);
                MMA_F16(oacc[di * 2 + 1], pf[ki][0], pf[ki][1], pf[ki][2],
                        pf[ki][3], v2, v3);
            }
        }
    };

    // ---- main loop: tiles 0..7 (keys 0..511, all valid) ----
    for (int kt = 0; kt < 8; kt++) {
        asm volatile("cp.async.wait_group 0;");
        __syncthreads();               // tile kt visible; buf (kt+1)&1 free
        ldKV(kt + 1);                  // kt+1 <= 8

        const uint32_t sK = sb + 8192 + (kt & 1) * 16384;
        const uint32_t sV = sK + 8192;
        const int k0 = kt * 64;

        float pv[8][4];
        computeS(sK, pv);
        if (k0 == q0) maskDiag(k0, pv);

        float vmax0 = -1e30f, vmax1 = -1e30f;
#pragma unroll
        for (int ni = 0; ni < 8; ni++) {
            vmax0 = fmaxf(vmax0, fmaxf(pv[ni][0], pv[ni][1]));
            vmax1 = fmaxf(vmax1, fmaxf(pv[ni][2], pv[ni][3]));
        }
        vmax0 = fmaxf(vmax0, __shfl_xor_sync(0xffffffffu, vmax0, 1));
        vmax0 = fmaxf(vmax0, __shfl_xor_sync(0xffffffffu, vmax0, 2));
        vmax1 = fmaxf(vmax1, __shfl_xor_sync(0xffffffffu, vmax1, 1));
        vmax1 = fmaxf(vmax1, __shfl_xor_sync(0xffffffffu, vmax1, 2));

        float mn0 = fmaxf(m0r, vmax0), mn1 = fmaxf(m1r, vmax1);
        float cr0 = ex2f(m0r - mn0), cr1 = ex2f(m1r - mn1);
        m0r = mn0; m1r = mn1;

        float s0 = 0.f, s1 = 0.f;
        uint32_t pf[4][4];
#pragma unroll
        for (int ni = 0; ni < 8; ni++) {
            float p0 = ex2f(pv[ni][0] - mn0);
            float p1 = ex2f(pv[ni][1] - mn0);
            float p2 = ex2f(pv[ni][2] - mn1);
            float p3 = ex2f(pv[ni][3] - mn1);
            s0 += p0 + p1;
            s1 += p2 + p3;
            pf[ni >> 1][(ni & 1) * 2 + 0] = pack_h2(p0, p1);
            pf[ni >> 1][(ni & 1) * 2 + 1] = pack_h2(p2, p3);
        }
        s0 += __shfl_xor_sync(0xffffffffu, s0, 1);
        s0 += __shfl_xor_sync(0xffffffffu, s0, 2);
        s1 += __shfl_xor_sync(0xffffffffu, s1, 1);
        s1 += __shfl_xor_sync(0xffffffffu, s1, 2);
        l0r = l0r * cr0 + s0;
        l1r = l1r * cr1 + s1;
#pragma unroll
        for (int nd = 0; nd < 8; nd++) {
            oacc[nd][0] *= cr0; oacc[nd][1] *= cr0;
            oacc[nd][2] *= cr1; oacc[nd][3] *= cr1;
        }

        pvMMA(sV, pf);
    }

    // ---- FINAL EPOCH: tile 8 (keys 512..575) + tail key 576, ONE state update --
    {
        asm volatile("cp.async.wait_group 0;");
        __syncthreads();                 // tile 8 (buf 0) visible; buf 1 free (tile 7 done)
        ldKV(9);                         // tail tile -> buf 1

        const uint32_t sK8 = sb + 8192,          sV8 = sK8 + 8192;   // buf 0
        const uint32_t sK9 = sb + 8192 + 16384,  sV9 = sK9 + 8192;   // buf 1

        // S for tile 8 (overlaps the tail cp.async)
        float pv[8][4];
        computeS(sK8, pv);
        if (q0 == 512) maskDiag(512, pv);

        // wait for tail tile, then its S column
        asm volatile("cp.async.wait_group 0;");
        __syncthreads();

        float st[4] = {0.f, 0.f, 0.f, 0.f};
#pragma unroll
        for (int k16 = 0; k16 < 4; k16++) {
            uint32_t r0, r1, r2, r3;
            int row = ((lid >> 4) & 1) * 8 + (lid & 7);
            uint32_t off = row * 128 + k16 * 32 + ((lid >> 3) & 1) * 16;
            uint32_t sw = off ^ ((off >> 3) & 0x70);
            LDSM_X4(r0, r1, r2, r3, sK9 + sw);
            MMA_F16(st, qf[k16][0], qf[k16][1], qf[k16][2], qf[k16][3], r0, r1);
        }
        float tv0 = (cbx == 0) ? st[0] : -1e30f;   // row gi0, col 576
        float tv1 = (cbx == 0) ? st[2] : -1e30f;   // row gi1
        if (gi0 == 576) tv0 = NEG2;
        if (gi1 == 576) tv1 = NEG2;

        // combined row-max over 65 keys
        float vmax0 = tv0, vmax1 = tv1;
#pragma unroll
        for (int ni = 0; ni < 8; ni++) {
            vmax0 = fmaxf(vmax0, fmaxf(pv[ni][0], pv[ni][1]));
            vmax1 = fmaxf(vmax1, fmaxf(pv[ni][2], pv[ni][3]));
        }
        vmax0 = fmaxf(vmax0, __shfl_xor_sync(0xffffffffu, vmax0, 1));
        vmax0 = fmaxf(vmax0, __shfl_xor_sync(0xffffffffu, vmax0, 2));
        vmax1 = fmaxf(vmax1, __shfl_xor_sync(0xffffffffu, vmax1, 1));
        vmax1 = fmaxf(vmax1, __shfl_xor_sync(0xffffffffu, vmax1, 2));

        float mn0 = fmaxf(m0r, vmax0), mn1 = fmaxf(m1r, vmax1);
        float cr0 = ex2f(m0r - mn0), cr1 = ex2f(m1r - mn1);
        m0r = mn0; m1r = mn1;

        // exp for tile 8 + tail; single partial-sum pass
        float s0 = 0.f, s1 = 0.f;
        uint32_t pf[4][4];
#pragma unroll
        for (int ni = 0; ni < 8; ni++) {
            float p0 = ex2f(pv[ni][0] - mn0);
            float p1 = ex2f(pv[ni][1] - mn0);
            float p2 = ex2f(pv[ni][2] - mn1);
            float p3 = ex2f(pv[ni][3] - mn1);
            s0 += p0 + p1;
            s1 += p2 + p3;
            pf[ni >> 1][(ni & 1) * 2 + 0] = pack_h2(p0, p1);
            pf[ni >> 1][(ni & 1) * 2 + 1] = pack_h2(p2, p3);
        }
        float tp0 = ex2f(tv0 - mn0), tp1 = ex2f(tv1 - mn1);
        s0 += tp0;
        s1 += tp1;
        s0 += __shfl_xor_sync(0xffffffffu, s0, 1);
        s0 += __shfl_xor_sync(0xffffffffu, s0, 2);
        s1 += __shfl_xor_sync(0xffffffffu, s1, 1);
        s1 += __shfl_xor_sync(0xffffffffu, s1, 2);
        l0r = l0r * cr0 + s0;
        l1r = l1r * cr1 + s1;
#pragma unroll
        for (int nd = 0; nd < 8; nd++) {
            oacc[nd][0] *= cr0; oacc[nd][1] *= cr0;
            oacc[nd][2] *= cr1; oacc[nd][3] *= cr1;
        }

        // PV for tile 8, then tail PV
        pvMMA(sV8, pf);

        uint32_t pa0 = pack_h2(tp0, 0.f);
        uint32_t pa1 = pack_h2(tp1, 0.f);
        uint32_t zz = 0u;
#pragma unroll
        for (int di = 0; di < 4; di++) {
            int row = (lid & 15);
            uint32_t off = row * 128 + di * 32 + (lid >> 4) * 16;
            uint32_t sw = off ^ ((off >> 3) & 0x70);
            uint32_t v0r, v1r, v2r, v3r;
            LDSM_X4_T(v0r, v1r, v2r, v3r, sV9 + sw);
            MMA_F16(oacc[di * 2],     pa0, pa1, zz, zz, v0r, v1r);
            MMA_F16(oacc[di * 2 + 1], pa0, pa1, zz, zz, v2r, v3r);
        }
    }

    float inv0 = 1.f / l0r, inv1 = 1.f / l1r;
    if (gi0 < N_) {
        __half* dst = g_atth + ((size_t)b * N_ + gi0) * INNER + h * 64 + cbx;
#pragma unroll
        for (int nd = 0; nd < 8; nd++)
            *(__half2*)(dst + nd * 8) = __floats2half2_rn(oacc[nd][0] * inv0,
                                                          oacc[nd][1] * inv0);
    }
    if (gi1 < N_) {
        __half* dst = g_atth + ((size_t)b * N_ + gi1) * INNER + h * 64 + cbx;
#pragma unroll
        for (int nd = 0; nd < 8; nd++)
            *(__half2*)(dst + nd * 8) = __floats2half2_rn(oacc[nd][2] * inv1,
                                                          oacc[nd][3] * inv1);
    }
}

// ---------------- launch --------------------------------------------------------
extern "C" void kernel_launch(void* const* d_in, const int* in_sizes, int n_in,
                              void* d_out, int out_size)
{
    const float* x      = (const float*)d_in[0];
    const float* W_qkv  = (const float*)d_in[1];
    const float* scale  = (const float*)d_in[2];
    const float* W_out  = (const float*)d_in[3];
    const float* b_out  = (const float*)d_in[4];
    float* out = (float*)d_out;
    (void)in_sizes; (void)n_in; (void)out_size;

    const int HGEMM_SMEM = 2 * 32768;          // 65536
    const int ATTN_SMEM  = 8192 + 2 * 16384;   // 40960
    cudaFuncSetAttribute(hgemm_mma, cudaFuncAttributeMaxDynamicSharedMemorySize,
                         HGEMM_SMEM);
    cudaFuncSetAttribute(attn_mma, cudaFuncAttributeMaxDynamicSharedMemorySize,
                         ATTN_SMEM);

    __half* xh;     cudaGetSymbolAddress((void**)&xh, g_xh);
    __half* atth;   cudaGetSymbolAddress((void**)&atth, g_atth);
    __half* wqkvt;  cudaGetSymbolAddress((void**)&wqkvt, g_wqkvt);
    __half* woutt;  cudaGetSymbolAddress((void**)&woutt, g_woutt);

    // 0) fused prologue: x -> fp16; W_qkv, W_out -> transposed fp16
    prologue_fused<<<NXB + NQB + NOB, 256>>>(x, xh, W_qkv, wqkvt, W_out, woutt);

    // 1) qkv projection (HMMA); q pre-scaled by scale[h]*log2e in epilogue
    hgemm_mma<<<dim3(2304 / 128, (M_TOT + 127) / 128), 128, HGEMM_SMEM>>>(
        xh, wqkvt, M_TOT, 0, nullptr, scale, nullptr);

    // 2) HMMA flash attention (log2-domain softmax, fused final epoch)
    attn_mma<<<dim3((N_ + 63) / 64, H_, B_), 128, ATTN_SMEM>>>();

    // 3) output projection + bias (HMMA)
    hgemm_mma<<<dim3(768 / 128, (M_TOT + 127) / 128), 128, HGEMM_SMEM>>>(
        atth, woutt, M_TOT, 1, b_out, nullptr, out);
}